// round 3
// baseline (speedup 1.0000x reference)
#include <cuda_runtime.h>

// GEMV: out[i] = dot(inputs[i,0:272], weights) + bias
// Warp-per-row, 32 contiguous rows per warp, weights register-resident.

#define NV4 272 / 4              // 68 float4 per row
#define WARPS_PER_BLOCK 8
#define THREADS (WARPS_PER_BLOCK * 32)
#define ROWS_PER_WARP 32
#define ROWS_PER_BLOCK (WARPS_PER_BLOCK * ROWS_PER_WARP)  // 256

__device__ __forceinline__ float weight_of(const float* sk, int c, float W1, float W2) {
    if (c < 16) return sk[c];
    const int p = c - 16;
    const int x1 = p >> 4, x2 = p & 15;
    const int a1 = x1 >> 2, b1 = x1 & 3;
    const int a2 = x2 >> 2, b2 = x2 & 3;
    return sk[4 * a1 + a2] * sk[4 * b1 + b2] * W1 +
           sk[4 * a1 + b2] * sk[4 * b1 + a2] * W2;
}

__global__ __launch_bounds__(THREADS) void gemv272_rw_kernel(
    const float* __restrict__ inputs,
    const float* __restrict__ kern,
    const float* __restrict__ w1p,
    const float* __restrict__ w2p,
    const float* __restrict__ biasp,
    float* __restrict__ out,
    int n)
{
    __shared__ float sk[16];
    const int t = threadIdx.x;
    if (t < 16) sk[t] = kern[t];
    __syncthreads();

    const float W1 = w1p[0], W2 = w2p[0], B = biasp[0];
    const int lane = t & 31;
    const int warp = t >> 5;

    // Per-lane register weights: columns 4l..4l+3, 128+4l.., 256+4l (lanes<4).
    float4 wA, wB, wC;
    {
        const int c0 = 4 * lane;
        wA.x = weight_of(sk, c0 + 0, W1, W2);
        wA.y = weight_of(sk, c0 + 1, W1, W2);
        wA.z = weight_of(sk, c0 + 2, W1, W2);
        wA.w = weight_of(sk, c0 + 3, W1, W2);
        const int c1 = 128 + 4 * lane;
        wB.x = weight_of(sk, c1 + 0, W1, W2);
        wB.y = weight_of(sk, c1 + 1, W1, W2);
        wB.z = weight_of(sk, c1 + 2, W1, W2);
        wB.w = weight_of(sk, c1 + 3, W1, W2);
        wC = make_float4(0.f, 0.f, 0.f, 0.f);
        if (lane < 4) {
            const int c2 = 256 + 4 * lane;
            wC.x = weight_of(sk, c2 + 0, W1, W2);
            wC.y = weight_of(sk, c2 + 1, W1, W2);
            wC.z = weight_of(sk, c2 + 2, W1, W2);
            wC.w = weight_of(sk, c2 + 3, W1, W2);
        }
    }

    const long base = ((long)blockIdx.x * WARPS_PER_BLOCK + warp) * ROWS_PER_WARP;
    float res = 0.f;

#pragma unroll 4
    for (int it = 0; it < ROWS_PER_WARP; ++it) {
        const long row = base + it;
        float acc = 0.f;
        if (row < n) {
            const float4* __restrict__ rp =
                reinterpret_cast<const float4*>(inputs) + row * NV4;
            const float4 v0 = rp[lane];
            const float4 v1 = rp[32 + lane];
            float4 v2 = make_float4(0.f, 0.f, 0.f, 0.f);
            if (lane < 4) v2 = rp[64 + lane];

            acc = v0.x * wA.x;
            acc = fmaf(v0.y, wA.y, acc);
            acc = fmaf(v0.z, wA.z, acc);
            acc = fmaf(v0.w, wA.w, acc);
            acc = fmaf(v1.x, wB.x, acc);
            acc = fmaf(v1.y, wB.y, acc);
            acc = fmaf(v1.z, wB.z, acc);
            acc = fmaf(v1.w, wB.w, acc);
            acc = fmaf(v2.x, wC.x, acc);
            acc = fmaf(v2.y, wC.y, acc);
            acc = fmaf(v2.z, wC.z, acc);
            acc = fmaf(v2.w, wC.w, acc);
        }
#pragma unroll
        for (int off = 16; off > 0; off >>= 1)
            acc += __shfl_xor_sync(0xFFFFFFFFu, acc, off);

        if (lane == it) res = acc + B;
    }

    const long orow = base + lane;
    if (orow < n) out[orow] = res;
}

extern "C" void kernel_launch(void* const* d_in, const int* in_sizes, int n_in,
                              void* d_out, int out_size)
{
    const float* inputs = (const float*)d_in[0];
    const float* kern   = (const float*)d_in[1];
    const float* w1     = (const float*)d_in[2];
    const float* w2     = (const float*)d_in[3];
    const float* bias   = (const float*)d_in[4];
    float* out = (float*)d_out;

    const int n = out_size;  // 500000
    const int blocks = (n + ROWS_PER_BLOCK - 1) / ROWS_PER_BLOCK;  // 1954
    gemv272_rw_kernel<<<blocks, THREADS>>>(inputs, kern, w1, w2, bias, out, n);
}

// round 4
// speedup vs baseline: 1.0169x; 1.0169x over previous
#include <cuda_runtime.h>

// GEMV: out[i] = dot(inputs[i,0:272], weights) + bias
// Warp handles 4 consecutive rows; register-resident weights; joint tree reduce.

#define NV4 (272 / 4)            // 68 float4 per row
#define WARPS_PER_BLOCK 8
#define THREADS (WARPS_PER_BLOCK * 32)
#define ROWS_PER_WARP 4
#define ROWS_PER_BLOCK (WARPS_PER_BLOCK * ROWS_PER_WARP)  // 32

__device__ __forceinline__ float weight_of(const float* sk, int c, float W1, float W2) {
    if (c < 16) return sk[c];
    const int p = c - 16;
    const int x1 = p >> 4, x2 = p & 15;
    const int a1 = x1 >> 2, b1 = x1 & 3;
    const int a2 = x2 >> 2, b2 = x2 & 3;
    return sk[4 * a1 + a2] * sk[4 * b1 + b2] * W1 +
           sk[4 * a1 + b2] * sk[4 * b1 + a2] * W2;
}

__device__ __forceinline__ float row_dot(const float4* __restrict__ rp, int lane,
                                         const float4& wA, const float4& wB,
                                         const float4& wC) {
    const float4 v0 = rp[lane];
    const float4 v1 = rp[32 + lane];
    float4 v2 = make_float4(0.f, 0.f, 0.f, 0.f);
    if (lane < 4) v2 = rp[64 + lane];
    float acc = v0.x * wA.x;
    acc = fmaf(v0.y, wA.y, acc);
    acc = fmaf(v0.z, wA.z, acc);
    acc = fmaf(v0.w, wA.w, acc);
    acc = fmaf(v1.x, wB.x, acc);
    acc = fmaf(v1.y, wB.y, acc);
    acc = fmaf(v1.z, wB.z, acc);
    acc = fmaf(v1.w, wB.w, acc);
    acc = fmaf(v2.x, wC.x, acc);
    acc = fmaf(v2.y, wC.y, acc);
    acc = fmaf(v2.z, wC.z, acc);
    acc = fmaf(v2.w, wC.w, acc);
    return acc;
}

__global__ __launch_bounds__(THREADS) void gemv272_r4_kernel(
    const float* __restrict__ inputs,
    const float* __restrict__ kern,
    const float* __restrict__ w1p,
    const float* __restrict__ w2p,
    const float* __restrict__ biasp,
    float* __restrict__ out,
    int n)
{
    __shared__ float sk[16];
    const int t = threadIdx.x;
    if (t < 16) sk[t] = kern[t];
    __syncthreads();

    const float W1 = w1p[0], W2 = w2p[0], B = biasp[0];
    const int lane = t & 31;
    const int warp = t >> 5;

    // Per-lane register weights: columns 4l..4l+3, 128+4l.., 256+4l (lanes<4).
    float4 wA, wB, wC;
    {
        const int c0 = 4 * lane;
        wA.x = weight_of(sk, c0 + 0, W1, W2);
        wA.y = weight_of(sk, c0 + 1, W1, W2);
        wA.z = weight_of(sk, c0 + 2, W1, W2);
        wA.w = weight_of(sk, c0 + 3, W1, W2);
        const int c1 = 128 + 4 * lane;
        wB.x = weight_of(sk, c1 + 0, W1, W2);
        wB.y = weight_of(sk, c1 + 1, W1, W2);
        wB.z = weight_of(sk, c1 + 2, W1, W2);
        wB.w = weight_of(sk, c1 + 3, W1, W2);
        wC = make_float4(0.f, 0.f, 0.f, 0.f);
        if (lane < 4) {
            const int c2 = 256 + 4 * lane;
            wC.x = weight_of(sk, c2 + 0, W1, W2);
            wC.y = weight_of(sk, c2 + 1, W1, W2);
            wC.z = weight_of(sk, c2 + 2, W1, W2);
            wC.w = weight_of(sk, c2 + 3, W1, W2);
        }
    }

    const long base = ((long)blockIdx.x * WARPS_PER_BLOCK + warp) * ROWS_PER_WARP;
    const float4* __restrict__ rp0 =
        reinterpret_cast<const float4*>(inputs) + base * NV4;

    // 4 independent row dots (12 LDGs issuable together).
    const bool full = (base + 3) < n;
    float a0 = 0.f, a1 = 0.f, a2 = 0.f, a3 = 0.f;
    if (full) {
        a0 = row_dot(rp0 + 0 * NV4, lane, wA, wB, wC);
        a1 = row_dot(rp0 + 1 * NV4, lane, wA, wB, wC);
        a2 = row_dot(rp0 + 2 * NV4, lane, wA, wB, wC);
        a3 = row_dot(rp0 + 3 * NV4, lane, wA, wB, wC);
    } else {
        if (base + 0 < n) a0 = row_dot(rp0 + 0 * NV4, lane, wA, wB, wC);
        if (base + 1 < n) a1 = row_dot(rp0 + 1 * NV4, lane, wA, wB, wC);
        if (base + 2 < n) a2 = row_dot(rp0 + 2 * NV4, lane, wA, wB, wC);
        if (base + 3 < n) a3 = row_dot(rp0 + 3 * NV4, lane, wA, wB, wC);
    }

    // Joint tree reduction: 9 shfls for 4 rows.
    a0 += __shfl_xor_sync(0xFFFFFFFFu, a0, 16);
    a1 += __shfl_xor_sync(0xFFFFFFFFu, a1, 16);
    a2 += __shfl_xor_sync(0xFFFFFFFFu, a2, 16);
    a3 += __shfl_xor_sync(0xFFFFFFFFu, a3, 16);
    float x = (lane & 16) ? a1 : a0;   // rows 0/1, halves by bit4
    float y = (lane & 16) ? a3 : a2;   // rows 2/3
    x += __shfl_xor_sync(0xFFFFFFFFu, x, 8);
    y += __shfl_xor_sync(0xFFFFFFFFu, y, 8);
    float z = (lane & 8) ? y : x;      // row = (bit4) | (bit3<<1)
    z += __shfl_xor_sync(0xFFFFFFFFu, z, 4);
    z += __shfl_xor_sync(0xFFFFFFFFu, z, 2);
    z += __shfl_xor_sync(0xFFFFFFFFu, z, 1);

    // Lane l holds total of row r = ((l>>4)&1) | (((l>>3)&1)<<1); writers: 0,16,8,24.
    const int r = ((lane >> 4) & 1) | (((lane >> 3) & 1) << 1);
    const bool writer = (lane & 7) == 0;
    const long orow = base + r;
    if (writer && orow < n) out[orow] = z + B;
}

extern "C" void kernel_launch(void* const* d_in, const int* in_sizes, int n_in,
                              void* d_out, int out_size)
{
    const float* inputs = (const float*)d_in[0];
    const float* kern   = (const float*)d_in[1];
    const float* w1     = (const float*)d_in[2];
    const float* w2     = (const float*)d_in[3];
    const float* bias   = (const float*)d_in[4];
    float* out = (float*)d_out;

    const int n = out_size;  // 500000
    const int blocks = (n + ROWS_PER_BLOCK - 1) / ROWS_PER_BLOCK;  // 15625
    gemv272_r4_kernel<<<blocks, THREADS>>>(inputs, kern, w1, w2, bias, out, n);
}